// round 10
// baseline (speedup 1.0000x reference)
#include <cuda_runtime.h>
#include <cuda_bf16.h>
#include <math.h>
#include <stdint.h>

// Problem constants
#define T_   1024
#define B_   8
#define D_   1024
#define H_   16
#define DH_  64
#define FF_  4096
#define M_   (T_ * B_)          // 8192
#define MD_  (8388608)          // M_ * D_
#define SCALE_ 0.125f
#define BG_  0.1f

// fp32 scratch (10 * MD): 0-2 qkv, 3-5 yW, 6-8 xU, 9 src
__device__ float g_buf[10ull * 8388608ull];
// bf16 split scratch: 22 units of MD elems
__device__ __nv_bfloat16 g_sp[22ull * 8388608ull];
// weight split scratch
__device__ __nv_bfloat16 g_Bh[4194304];
__device__ __nv_bfloat16 g_Bl[4194304];

// ---------------------------------------------------------------------------
// PTX helpers
// ---------------------------------------------------------------------------
__device__ __forceinline__ uint32_t smem_u32(const void* p) {
    uint32_t a;
    asm("{ .reg .u64 t; cvta.to.shared.u64 t, %1; cvt.u32.u64 %0, t; }"
        : "=r"(a) : "l"(p));
    return a;
}
__device__ __forceinline__ void cp16(uint32_t s, const void* g) {
    asm volatile("cp.async.cg.shared.global [%0], [%1], 16;" :: "r"(s), "l"(g));
}
__device__ __forceinline__ void cp_commit() {
    asm volatile("cp.async.commit_group;" ::: "memory");
}
__device__ __forceinline__ void cp_wait1() {
    asm volatile("cp.async.wait_group 1;" ::: "memory");
}
__device__ __forceinline__ void ldsm4(uint32_t (&r)[4], uint32_t addr) {
    asm volatile("ldmatrix.sync.aligned.m8n8.x4.shared.b16 {%0,%1,%2,%3}, [%4];"
        : "=r"(r[0]), "=r"(r[1]), "=r"(r[2]), "=r"(r[3]) : "r"(addr));
}
#define MMA(d, a, b) \
    asm volatile("mma.sync.aligned.m16n8k16.row.col.f32.bf16.bf16.f32 " \
        "{%0,%1,%2,%3}, {%4,%5,%6,%7}, {%8,%9}, {%0,%1,%2,%3};" \
        : "+f"((d)[0]), "+f"((d)[1]), "+f"((d)[2]), "+f"((d)[3]) \
        : "r"((a)[0]), "r"((a)[1]), "r"((a)[2]), "r"((a)[3]), \
          "r"((b)[0]), "r"((b)[1]))

__device__ __forceinline__ void split1(float v, __nv_bfloat16& h, __nv_bfloat16& l) {
    h = __float2bfloat16_rn(v);
    l = __float2bfloat16_rn(v - __bfloat162float(h));
}

// ---------------------------------------------------------------------------
// fp32 -> bf16 hi/lo split (elementwise)
// ---------------------------------------------------------------------------
__global__ __launch_bounds__(256) void splitA_kernel(
    const float* __restrict__ in, __nv_bfloat16* __restrict__ oh,
    __nv_bfloat16* __restrict__ ol, int n4)
{
    int i = blockIdx.x * 256 + threadIdx.x;
    if (i >= n4) return;
    float4 v = ((const float4*)in)[i];
    float vv[4] = {v.x, v.y, v.z, v.w};
    __nv_bfloat16 h[4], l[4];
    #pragma unroll
    for (int j = 0; j < 4; j++) split1(vv[j], h[j], l[j]);
    ((__nv_bfloat162*)oh)[2 * i]     = __nv_bfloat162(h[0], h[1]);
    ((__nv_bfloat162*)oh)[2 * i + 1] = __nv_bfloat162(h[2], h[3]);
    ((__nv_bfloat162*)ol)[2 * i]     = __nv_bfloat162(l[0], l[1]);
    ((__nv_bfloat162*)ol)[2 * i + 1] = __nv_bfloat162(l[2], l[3]);
}

// ---------------------------------------------------------------------------
// Weight transpose + split: in fp32 [K,N] -> out bf16 [N,K] hi/lo
// ---------------------------------------------------------------------------
__global__ __launch_bounds__(256) void transB_kernel(
    const float* __restrict__ in, __nv_bfloat16* __restrict__ oh,
    __nv_bfloat16* __restrict__ ol, int Kd, int Nd)
{
    __shared__ float t[32][33];
    int n0 = blockIdx.x * 32, k0 = blockIdx.y * 32;
    int tx = threadIdx.x, ty = threadIdx.y;      // (32, 8)
    #pragma unroll
    for (int j = 0; j < 32; j += 8)
        t[ty + j][tx] = in[(size_t)(k0 + ty + j) * Nd + n0 + tx];
    __syncthreads();
    #pragma unroll
    for (int j = 0; j < 32; j += 8) {
        __nv_bfloat16 h, l;
        split1(t[tx][ty + j], h, l);
        size_t o = (size_t)(n0 + ty + j) * Kd + k0 + tx;
        oh[o] = h; ol[o] = l;
    }
}

// ---------------------------------------------------------------------------
// bf16-split GEMM: C[M,N] = A[M,K] @ Bt[N,K]^T (fp32-equivalent accuracy)
// 128x128x32 CTA tile, 8 warps (32x64 each), 3-stage cp.async pipeline,
// ONE barrier per K-tile (stage t+2 == stage t-1, whose readers passed the
// top barrier). Epilogue mode is a template param so each instantiation
// compiles a single tight path (no register tax on the mainloop).
// ---------------------------------------------------------------------------
#define BM 128
#define BN 128
#define BK 32
#define STAGES 3
#define AROW 40                             // padded row stride (bf16 elems)
#define MAT_BYTES (BM * AROW * 2)           // 10240
#define STAGE_BYTES (4 * MAT_BYTES)         // 40960
#define GEMM_SMEM (STAGES * STAGE_BYTES)    // 122880

template<int OSPLIT>
__global__ __launch_bounds__(256) void mma_gemm(
    const __nv_bfloat16* __restrict__ Ah, const __nv_bfloat16* __restrict__ Al,
    const __nv_bfloat16* __restrict__ Bh, const __nv_bfloat16* __restrict__ Bl,
    float* __restrict__ C, __nv_bfloat16* __restrict__ Ch,
    __nv_bfloat16* __restrict__ Cl,
    int M, int N, int K, const float* __restrict__ bias, int relu)
{
    extern __shared__ char smem[];
    const uint32_t sbase = smem_u32(smem);
    const int tid = threadIdx.x, wid = tid >> 5, lane = tid & 31;
    const int wm = wid & 3, wn = wid >> 2;          // warp tile (32m x 64n)
    const size_t arow0 = (size_t)blockIdx.y * BM;
    const size_t brow0 = (size_t)blockIdx.x * BN;
    const __nv_bfloat16* srcs[4] = {
        Ah + arow0 * K, Al + arow0 * K, Bh + brow0 * K, Bl + brow0 * K };
    const int KT = K / BK;

    const int crow0_ld = tid >> 2, c16 = tid & 3;

    const int lrowA = lane & 15;
    const int lcolA = (lane >> 4) * 8;
    const int lrowB = (lane & 7) + ((lane >> 4) << 3);
    const int lcolB = ((lane >> 3) & 1) * 8;

    float acc[2][8][4];
    #pragma unroll
    for (int i = 0; i < 2; i++)
        #pragma unroll
        for (int j = 0; j < 8; j++)
            #pragma unroll
            for (int q = 0; q < 4; q++) acc[i][j][q] = 0.f;

    auto load_stage = [&](int t) {
        uint32_t sb = sbase + (uint32_t)(t % STAGES) * STAGE_BYTES;
        size_t koff = (size_t)t * BK;
        #pragma unroll
        for (int m = 0; m < 4; m++) {
            const __nv_bfloat16* g = srcs[m] + koff;
            uint32_t sm = sb + m * MAT_BYTES;
            #pragma unroll
            for (int j = 0; j < 2; j++) {
                int row = crow0_ld + j * 64;
                cp16(sm + (uint32_t)(row * AROW + c16 * 8) * 2,
                     (const char*)(g + (size_t)row * K) + c16 * 16);
            }
        }
        cp_commit();
    };

    load_stage(0);
    load_stage(1);

    for (int t = 0; t < KT; t++) {
        cp_wait1();                 // stage t resident
        __syncthreads();            // all warps past tile t-1 reads
        if (t + STAGES - 1 < KT) load_stage(t + STAGES - 1);

        uint32_t sb  = sbase + (uint32_t)(t % STAGES) * STAGE_BYTES;
        uint32_t sAh = sb, sAl = sb + MAT_BYTES;
        uint32_t sBh = sb + 2 * MAT_BYTES, sBl = sb + 3 * MAT_BYTES;

        #pragma unroll
        for (int kk = 0; kk < BK; kk += 16) {
            uint32_t aH[2][4], aL[2][4], bH[8][2], bL[8][2];
            #pragma unroll
            for (int mi = 0; mi < 2; mi++) {
                uint32_t off =
                    (uint32_t)((wm * 32 + mi * 16 + lrowA) * AROW + kk + lcolA) * 2;
                ldsm4(aH[mi], sAh + off);
                ldsm4(aL[mi], sAl + off);
            }
            #pragma unroll
            for (int np = 0; np < 4; np++) {
                uint32_t off =
                    (uint32_t)((wn * 64 + np * 16 + lrowB) * AROW + kk + lcolB) * 2;
                uint32_t r[4];
                ldsm4(r, sBh + off);
                bH[2 * np][0] = r[0]; bH[2 * np][1] = r[1];
                bH[2 * np + 1][0] = r[2]; bH[2 * np + 1][1] = r[3];
                ldsm4(r, sBl + off);
                bL[2 * np][0] = r[0]; bL[2 * np][1] = r[1];
                bL[2 * np + 1][0] = r[2]; bL[2 * np + 1][1] = r[3];
            }
            #pragma unroll
            for (int mi = 0; mi < 2; mi++)
                #pragma unroll
                for (int ni = 0; ni < 8; ni++) {
                    MMA(acc[mi][ni], aH[mi], bH[ni]);
                    MMA(acc[mi][ni], aH[mi], bL[ni]);
                    MMA(acc[mi][ni], aL[mi], bH[ni]);
                }
        }
        // no bottom barrier: stage (t+2)%3 == (t-1)%3 and its readers all
        // passed the top barrier of this iteration before load_stage(t+2).
    }

    // epilogue: registers -> GMEM, fused bias/relu; single compiled path
    const int g = lane >> 2, tq = (lane & 3) * 2;
    const int crow = blockIdx.y * BM + wm * 32;
    const int ccol = blockIdx.x * BN + wn * 64;
    #pragma unroll
    for (int mi = 0; mi < 2; mi++) {
        #pragma unroll
        for (int ni = 0; ni < 8; ni++) {
            int row = crow + mi * 16 + g;
            int col = ccol + ni * 8 + tq;
            float2 v0 = make_float2(acc[mi][ni][0], acc[mi][ni][1]);
            float2 v1 = make_float2(acc[mi][ni][2], acc[mi][ni][3]);
            if (bias) {
                float2 bv = *(const float2*)(bias + col);
                v0.x += bv.x; v0.y += bv.y; v1.x += bv.x; v1.y += bv.y;
            }
            if (relu) {
                v0.x = fmaxf(v0.x, 0.f); v0.y = fmaxf(v0.y, 0.f);
                v1.x = fmaxf(v1.x, 0.f); v1.y = fmaxf(v1.y, 0.f);
            }
            if (OSPLIT == 0) {
                *(float2*)&C[(size_t)row * N + col]       = v0;
                *(float2*)&C[(size_t)(row + 8) * N + col] = v1;
            } else {
                __nv_bfloat16 h0, l0, h1, l1;
                split1(v0.x, h0, l0); split1(v0.y, h1, l1);
                *(__nv_bfloat162*)&Ch[(size_t)row * N + col] = __nv_bfloat162(h0, h1);
                *(__nv_bfloat162*)&Cl[(size_t)row * N + col] = __nv_bfloat162(l0, l1);
                split1(v1.x, h0, l0); split1(v1.y, h1, l1);
                *(__nv_bfloat162*)&Ch[(size_t)(row + 8) * N + col] = __nv_bfloat162(h0, h1);
                *(__nv_bfloat162*)&Cl[(size_t)(row + 8) * N + col] = __nv_bfloat162(l0, l1);
            }
        }
    }
}

// ---------------------------------------------------------------------------
// LayerNorm with fused bf16 hi/lo split output
// ---------------------------------------------------------------------------
__global__ __launch_bounds__(256) void ln_split_kernel(
    const float* __restrict__ x, const float* __restrict__ g,
    const float* __restrict__ b,
    __nv_bfloat16* __restrict__ oh, __nv_bfloat16* __restrict__ ol)
{
    int row = blockIdx.x;
    const float* xr = x + (size_t)row * D_;
    float s = 0.f, s2 = 0.f;
    #pragma unroll
    for (int i = threadIdx.x; i < D_; i += 256) {
        float v = xr[i]; s += v; s2 += v * v;
    }
    __shared__ float sh[20];
    #pragma unroll
    for (int o = 16; o > 0; o >>= 1) {
        s  += __shfl_down_sync(0xffffffffu, s,  o);
        s2 += __shfl_down_sync(0xffffffffu, s2, o);
    }
    int warp = threadIdx.x >> 5, lane = threadIdx.x & 31;
    if (lane == 0) { sh[warp] = s; sh[warp + 8] = s2; }
    __syncthreads();
    if (threadIdx.x == 0) {
        float ts = 0.f, ts2 = 0.f;
        #pragma unroll
        for (int w = 0; w < 8; w++) { ts += sh[w]; ts2 += sh[w + 8]; }
        float mean = ts * (1.0f / D_);
        float var  = ts2 * (1.0f / D_) - mean * mean;
        sh[16] = mean;
        sh[17] = rsqrtf(var + 1e-5f);
    }
    __syncthreads();
    float mean = sh[16], inv = sh[17];
    #pragma unroll
    for (int i = threadIdx.x; i < D_; i += 256) {
        float v = (xr[i] - mean) * inv * g[i] + b[i];
        __nv_bfloat16 h, l;
        split1(v, h, l);
        size_t o = (size_t)row * D_ + i;
        oh[o] = h; ol[o] = l;
    }
}

// ---------------------------------------------------------------------------
// Causal flash attention v2: float4 SMEM reads, chunk-16 deferred rescale,
// bf16 split output. qkv packed [M, 3072] (row = t*B + b).
// ---------------------------------------------------------------------------
#define QKV_S 3072
__global__ __launch_bounds__(128) void attn_kernel(
    const float* __restrict__ qkv,
    __nv_bfloat16* __restrict__ oh, __nv_bfloat16* __restrict__ ol)
{
    __shared__ float4 Ks[64 * 16];
    __shared__ float4 Vs[64 * 16];
    const int bh = blockIdx.y;
    const int bb = bh >> 4, hh = bh & 15;
    const int i  = blockIdx.x * 128 + threadIdx.x;
    const size_t colq = (size_t)hh * DH_;

    float qr[DH_];
    const float* qrow = qkv + (size_t)(i * B_ + bb) * QKV_S + colq;
    #pragma unroll
    for (int d = 0; d < DH_; d++) qr[d] = qrow[d] * SCALE_;

    float m = -INFINITY, l = 0.f;
    float acc[DH_];
    #pragma unroll
    for (int d = 0; d < DH_; d++) acc[d] = 0.f;

    const int jend = blockIdx.x * 128 + 127;
    const int jr = threadIdx.x >> 1;
    const int c0 = (threadIdx.x & 1) * 8;            // float4 units

    for (int j0 = 0; j0 <= jend; j0 += 64) {
        const float* kb = qkv + (size_t)((j0 + jr) * B_ + bb) * QKV_S + colq;
        #pragma unroll
        for (int c = 0; c < 8; c++) {
            Ks[jr * 16 + c0 + c] = ((const float4*)(kb + 1024))[c0 + c];
            Vs[jr * 16 + c0 + c] = ((const float4*)(kb + 2048))[c0 + c];
        }
        __syncthreads();

        #pragma unroll
        for (int cb = 0; cb < 64; cb += 16) {
            float p[16];
            float cmax = -INFINITY;
            #pragma unroll
            for (int jj = 0; jj < 16; jj++) {
                const float4* kr = &Ks[(cb + jj) * 16];
                float s = 0.f;
                #pragma unroll
                for (int d4 = 0; d4 < 16; d4++) {
                    float4 f = kr[d4];
                    s = fmaf(qr[4 * d4 + 0], f.x, s);
                    s = fmaf(qr[4 * d4 + 1], f.y, s);
                    s = fmaf(qr[4 * d4 + 2], f.z, s);
                    s = fmaf(qr[4 * d4 + 3], f.w, s);
                }
                int j = j0 + cb + jj;
                s = (j <= i) ? s : -INFINITY;
                p[jj] = s;
                cmax = fmaxf(cmax, s);
            }
            float mn = fmaxf(m, cmax);
            float corr = __expf(m - mn);
            float sump = 0.f;
            #pragma unroll
            for (int jj = 0; jj < 16; jj++) {
                p[jj] = __expf(p[jj] - mn);
                sump += p[jj];
            }
            l = l * corr + sump;
            #pragma unroll
            for (int d = 0; d < DH_; d++) acc[d] *= corr;
            #pragma unroll
            for (int jj = 0; jj < 16; jj++) {
                float pj = p[jj];
                const float4* vr = &Vs[(cb + jj) * 16];
                #pragma unroll
                for (int d4 = 0; d4 < 16; d4++) {
                    float4 f = vr[d4];
                    acc[4 * d4 + 0] = fmaf(pj, f.x, acc[4 * d4 + 0]);
                    acc[4 * d4 + 1] = fmaf(pj, f.y, acc[4 * d4 + 1]);
                    acc[4 * d4 + 2] = fmaf(pj, f.z, acc[4 * d4 + 2]);
                    acc[4 * d4 + 3] = fmaf(pj, f.w, acc[4 * d4 + 3]);
                }
            }
            m = mn;
        }
        __syncthreads();
    }

    float invl = 1.0f / l;
    size_t base = (size_t)(i * B_ + bb) * (H_ * DH_) + colq;
    #pragma unroll
    for (int d = 0; d < DH_; d += 2) {
        float v0 = acc[d] * invl, v1 = acc[d + 1] * invl;
        __nv_bfloat16 h0, l0, h1, l1;
        split1(v0, h0, l0); split1(v1, h1, l1);
        *(__nv_bfloat162*)&oh[base + d] = __nv_bfloat162(h0, h1);
        *(__nv_bfloat162*)&ol[base + d] = __nv_bfloat162(l0, l1);
    }
}

// ---------------------------------------------------------------------------
// GRU gate: yW/xU packed [M, 3072] (r|z|g). Optional bf16 split output.
// ---------------------------------------------------------------------------
__global__ __launch_bounds__(256) void gru_kernel(
    const float* __restrict__ x,
    const float* __restrict__ yW, const float* __restrict__ xU,
    const float* __restrict__ bz, float* __restrict__ out,
    __nv_bfloat16* __restrict__ oh, __nv_bfloat16* __restrict__ ol)
{
    int idx = blockIdx.x * 256 + threadIdx.x;
    int row = idx >> 10, d = idx & (D_ - 1);
    size_t b = (size_t)row * 3072 + d;
    float r = 1.0f / (1.0f + expf(-(yW[b] + xU[b])));
    float z = 1.0f / (1.0f + expf(-(yW[b + 1024] + xU[b + 1024] + bz[d] - BG_)));
    float h = tanhf(yW[b + 2048] + r * xU[b + 2048]);
    float v = (1.0f - z) * x[idx] + z * h;
    out[idx] = v;
    if (oh) {
        __nv_bfloat16 hh, ll;
        split1(v, hh, ll);
        oh[idx] = hh; ol[idx] = ll;
    }
}

// ---------------------------------------------------------------------------
static void conv_B(const float* w, __nv_bfloat16* bh, __nv_bfloat16* bl,
                   int K, int N, size_t outRowOff) {
    dim3 g(N / 32, K / 32), b(32, 8);
    transB_kernel<<<g, b>>>(w, bh + outRowOff * K, bl + outRowOff * K, K, N);
}

extern "C" void kernel_launch(void* const* d_in, const int* in_sizes, int n_in,
                              void* d_out, int out_size)
{
    const float* x     = (const float*)d_in[0];
    const float* Wq    = (const float*)d_in[1];
    const float* Wk    = (const float*)d_in[2];
    const float* Wv    = (const float*)d_in[3];
    const float* Wo    = (const float*)d_in[4];
    const float* ln1_g = (const float*)d_in[5];
    const float* ln1_b = (const float*)d_in[6];
    const float* W1    = (const float*)d_in[7];
    const float* b1    = (const float*)d_in[8];
    const float* W2    = (const float*)d_in[9];
    const float* b2    = (const float*)d_in[10];
    const float* ln2_g = (const float*)d_in[11];
    const float* ln2_b = (const float*)d_in[12];
    const float* g1W   = (const float*)d_in[13];
    const float* g1U   = (const float*)d_in[14];
    const float* g1bz  = (const float*)d_in[15];
    const float* g2W   = (const float*)d_in[16];
    const float* g2U   = (const float*)d_in[17];
    const float* g2bz  = (const float*)d_in[18];
    float* out = (float*)d_out;

    float* buf = nullptr;
    __nv_bfloat16 *sp = nullptr, *Bh = nullptr, *Bl = nullptr;
    cudaGetSymbolAddress((void**)&buf, g_buf);
    cudaGetSymbolAddress((void**)&sp, g_sp);
    cudaGetSymbolAddress((void**)&Bh, g_Bh);
    cudaGetSymbolAddress((void**)&Bl, g_Bl);

    float* qkv = buf + 0ull * MD_;      // [M, 3072]
    float* yW  = buf + 3ull * MD_;      // [M, 3072]
    float* xU  = buf + 6ull * MD_;      // [M, 3072]
    float* src = buf + 9ull * MD_;

    __nv_bfloat16* Anh = sp + 0ull  * MD_;
    __nv_bfloat16* Anl = sp + 1ull  * MD_;
    __nv_bfloat16* xh  = sp + 2ull  * MD_;
    __nv_bfloat16* xl  = sp + 3ull  * MD_;
    __nv_bfloat16* aoh = sp + 4ull  * MD_;
    __nv_bfloat16* aol = sp + 5ull  * MD_;
    __nv_bfloat16* yh  = sp + 6ull  * MD_;
    __nv_bfloat16* yl  = sp + 7ull  * MD_;
    __nv_bfloat16* sh  = sp + 8ull  * MD_;
    __nv_bfloat16* sl  = sp + 9ull  * MD_;
    __nv_bfloat16* snh = sp + 10ull * MD_;
    __nv_bfloat16* snl = sp + 11ull * MD_;
    __nv_bfloat16* f1h = sp + 12ull * MD_;   // [M, 4096]
    __nv_bfloat16* f1l = sp + 16ull * MD_;
    __nv_bfloat16* foh = sp + 20ull * MD_;
    __nv_bfloat16* fol = sp + 21ull * MD_;

    cudaFuncSetAttribute(mma_gemm<0>, cudaFuncAttributeMaxDynamicSharedMemorySize,
                         GEMM_SMEM);
    cudaFuncSetAttribute(mma_gemm<1>, cudaFuncAttributeMaxDynamicSharedMemorySize,
                         GEMM_SMEM);

    const size_t DD = (size_t)D_ * D_;
    const dim3 g3(3072 / BN, M_ / BM);    // (24, 64)
    const dim3 g1kk(1024 / BN, M_ / BM);  // (8, 64)
    const dim3 g4k(4096 / BN, M_ / BM);   // (32, 64)

    // --- LN1 (split out) + QKV ---
    ln_split_kernel<<<M_, 256>>>(x, ln1_g, ln1_b, Anh, Anl);
    conv_B(Wq, Bh, Bl, D_, D_, 0);
    conv_B(Wk, Bh, Bl, D_, D_, 1024);
    conv_B(Wv, Bh, Bl, D_, D_, 2048);
    mma_gemm<0><<<g3, 256, GEMM_SMEM>>>(Anh, Anl, Bh, Bl, qkv, nullptr, nullptr,
                                        M_, 3072, D_, nullptr, 0);

    // --- attention (split out) ---
    attn_kernel<<<dim3(T_ / 128, B_ * H_), 128>>>(qkv, aoh, aol);

    // --- output projection (split out y) ---
    conv_B(Wo, Bh, Bl, D_, D_, 0);
    mma_gemm<1><<<g1kk, 256, GEMM_SMEM>>>(aoh, aol, Bh, Bl, nullptr, yh, yl,
                                          M_, 1024, D_, nullptr, 0);

    // --- GRU gate 1 ---
    for (int i = 0; i < 3; i++) conv_B(g1W + i * DD, Bh, Bl, D_, D_, (size_t)i * 1024);
    mma_gemm<0><<<g3, 256, GEMM_SMEM>>>(yh, yl, Bh, Bl, yW, nullptr, nullptr,
                                        M_, 3072, D_, nullptr, 0);
    splitA_kernel<<<MD_ / 1024, 256>>>(x, xh, xl, MD_ / 4);
    for (int i = 0; i < 3; i++) conv_B(g1U + i * DD, Bh, Bl, D_, D_, (size_t)i * 1024);
    mma_gemm<0><<<g3, 256, GEMM_SMEM>>>(xh, xl, Bh, Bl, xU, nullptr, nullptr,
                                        M_, 3072, D_, nullptr, 0);
    gru_kernel<<<MD_ / 256, 256>>>(x, yW, xU, g1bz, src, sh, sl);

    // --- LN2 (split out) + FFN ---
    ln_split_kernel<<<M_, 256>>>(src, ln2_g, ln2_b, snh, snl);
    conv_B(W1, Bh, Bl, D_, FF_, 0);
    mma_gemm<1><<<g4k, 256, GEMM_SMEM>>>(snh, snl, Bh, Bl, nullptr, f1h, f1l,
                                         M_, 4096, D_, b1, 1);
    conv_B(W2, Bh, Bl, FF_, D_, 0);
    mma_gemm<1><<<g1kk, 256, GEMM_SMEM>>>(f1h, f1l, Bh, Bl, nullptr, foh, fol,
                                          M_, 1024, FF_, b2, 0);

    // --- GRU gate 2 ---
    for (int i = 0; i < 3; i++) conv_B(g2W + i * DD, Bh, Bl, D_, D_, (size_t)i * 1024);
    mma_gemm<0><<<g3, 256, GEMM_SMEM>>>(foh, fol, Bh, Bl, yW, nullptr, nullptr,
                                        M_, 3072, D_, nullptr, 0);
    for (int i = 0; i < 3; i++) conv_B(g2U + i * DD, Bh, Bl, D_, D_, (size_t)i * 1024);
    mma_gemm<0><<<g3, 256, GEMM_SMEM>>>(sh, sl, Bh, Bl, xU, nullptr, nullptr,
                                        M_, 3072, D_, nullptr, 0);
    gru_kernel<<<MD_ / 256, 256>>>(src, yW, xU, g2bz, out, nullptr, nullptr);
}

// round 11
// speedup vs baseline: 1.1320x; 1.1320x over previous
#include <cuda_runtime.h>
#include <cuda_bf16.h>
#include <math.h>
#include <stdint.h>

// Problem constants
#define T_   1024
#define B_   8
#define D_   1024
#define H_   16
#define DH_  64
#define FF_  4096
#define M_   (T_ * B_)          // 8192
#define MD_  (8388608)          // M_ * D_
#define SCALE_ 0.125f
#define BG_  0.1f

// fp32 scratch:
// 0:xn 1-3:qkv 4:attnb 5:y 6-8:yW 9-11:xU 12:src 13:sn 14:ffo 15-18:ff1
__device__ float g_buf[19ull * 8388608ull];
// bf16 split scratch
__device__ __nv_bfloat16 g_Ah[33554432];
__device__ __nv_bfloat16 g_Al[33554432];
__device__ __nv_bfloat16 g_Bh[4194304];
__device__ __nv_bfloat16 g_Bl[4194304];

// ---------------------------------------------------------------------------
// PTX helpers
// ---------------------------------------------------------------------------
__device__ __forceinline__ uint32_t smem_u32(const void* p) {
    uint32_t a;
    asm("{ .reg .u64 t; cvta.to.shared.u64 t, %1; cvt.u32.u64 %0, t; }"
        : "=r"(a) : "l"(p));
    return a;
}
__device__ __forceinline__ void cp16(uint32_t s, const void* g) {
    asm volatile("cp.async.cg.shared.global [%0], [%1], 16;" :: "r"(s), "l"(g));
}
__device__ __forceinline__ void cp_commit() {
    asm volatile("cp.async.commit_group;" ::: "memory");
}
__device__ __forceinline__ void cp_wait1() {
    asm volatile("cp.async.wait_group 1;" ::: "memory");
}
__device__ __forceinline__ void ldsm4(uint32_t (&r)[4], uint32_t addr) {
    asm volatile("ldmatrix.sync.aligned.m8n8.x4.shared.b16 {%0,%1,%2,%3}, [%4];"
        : "=r"(r[0]), "=r"(r[1]), "=r"(r[2]), "=r"(r[3]) : "r"(addr));
}
#define MMA(d, a, b) \
    asm volatile("mma.sync.aligned.m16n8k16.row.col.f32.bf16.bf16.f32 " \
        "{%0,%1,%2,%3}, {%4,%5,%6,%7}, {%8,%9}, {%0,%1,%2,%3};" \
        : "+f"((d)[0]), "+f"((d)[1]), "+f"((d)[2]), "+f"((d)[3]) \
        : "r"((a)[0]), "r"((a)[1]), "r"((a)[2]), "r"((a)[3]), \
          "r"((b)[0]), "r"((b)[1]))

__device__ __forceinline__ void split1(float v, __nv_bfloat16& h, __nv_bfloat16& l) {
    h = __float2bfloat16_rn(v);
    l = __float2bfloat16_rn(v - __bfloat162float(h));
}

// ---------------------------------------------------------------------------
// fp32 -> bf16 hi/lo split (elementwise, float4 vectorized)
// ---------------------------------------------------------------------------
__global__ __launch_bounds__(256) void splitA_kernel(
    const float* __restrict__ in, __nv_bfloat16* __restrict__ oh,
    __nv_bfloat16* __restrict__ ol, int n4)
{
    int i = blockIdx.x * 256 + threadIdx.x;
    if (i >= n4) return;
    float4 v = ((const float4*)in)[i];
    float vv[4] = {v.x, v.y, v.z, v.w};
    __nv_bfloat16 h[4], l[4];
    #pragma unroll
    for (int j = 0; j < 4; j++) split1(vv[j], h[j], l[j]);
    ((__nv_bfloat162*)oh)[2 * i]     = __nv_bfloat162(h[0], h[1]);
    ((__nv_bfloat162*)oh)[2 * i + 1] = __nv_bfloat162(h[2], h[3]);
    ((__nv_bfloat162*)ol)[2 * i]     = __nv_bfloat162(l[0], l[1]);
    ((__nv_bfloat162*)ol)[2 * i + 1] = __nv_bfloat162(l[2], l[3]);
}

// ---------------------------------------------------------------------------
// Weight transpose + split: in fp32 [K,N] -> out bf16 [N,K] hi/lo
// ---------------------------------------------------------------------------
__global__ __launch_bounds__(256) void transB_kernel(
    const float* __restrict__ in, __nv_bfloat16* __restrict__ oh,
    __nv_bfloat16* __restrict__ ol, int Kd, int Nd)
{
    __shared__ float t[32][33];
    int n0 = blockIdx.x * 32, k0 = blockIdx.y * 32;
    int tx = threadIdx.x, ty = threadIdx.y;      // (32, 8)
    #pragma unroll
    for (int j = 0; j < 32; j += 8)
        t[ty + j][tx] = in[(size_t)(k0 + ty + j) * Nd + n0 + tx];
    __syncthreads();
    #pragma unroll
    for (int j = 0; j < 32; j += 8) {
        __nv_bfloat16 h, l;
        split1(t[tx][ty + j], h, l);
        size_t o = (size_t)(n0 + ty + j) * Kd + k0 + tx;
        oh[o] = h; ol[o] = l;
    }
}

// ---------------------------------------------------------------------------
// bf16-split GEMM: C[M,N] = A[M,K] @ Bt[N,K]^T (fp32-equivalent accuracy)
// CTA 256x128x32, 8 warps (64x64 each), 3-stage cp.async, 1 barrier/K-tile.
// fp32 output only (R4 glue), fused bias/relu.
// ---------------------------------------------------------------------------
#define BM 256
#define BN 128
#define BK 32
#define STAGES 3
#define AROW 40                                // padded row stride (bf16)
#define A_BYTES (BM * AROW * 2)                // 20480
#define B_BYTES (BN * AROW * 2)                // 10240
#define STG_BYTES (2 * A_BYTES + 2 * B_BYTES)  // 61440
#define GEMM_SMEM (STAGES * STG_BYTES)         // 184320

__global__ __launch_bounds__(256) void mma_gemm(
    const __nv_bfloat16* __restrict__ Ah, const __nv_bfloat16* __restrict__ Al,
    const __nv_bfloat16* __restrict__ Bh, const __nv_bfloat16* __restrict__ Bl,
    float* __restrict__ C, int M, int N, int K,
    const float* __restrict__ bias, int relu)
{
    extern __shared__ char smem[];
    const uint32_t sbase = smem_u32(smem);
    const int tid = threadIdx.x, wid = tid >> 5, lane = tid & 31;
    const int wm = wid & 3, wn = wid >> 2;          // warp tile 64m x 64n
    const size_t arow0 = (size_t)blockIdx.y * BM;
    const size_t brow0 = (size_t)blockIdx.x * BN;
    const __nv_bfloat16* gA[2] = { Ah + arow0 * K, Al + arow0 * K };
    const __nv_bfloat16* gB[2] = { Bh + brow0 * K, Bl + brow0 * K };
    const int KT = K / BK;

    auto load_stage = [&](int t) {
        uint32_t sb = sbase + (uint32_t)(t % STAGES) * STG_BYTES;
        size_t ko = (size_t)t * BK;
        #pragma unroll
        for (int h = 0; h < 2; h++) {
            #pragma unroll
            for (int j = 0; j < 4; j++) {          // A: 1024 16B-chunks
                int cid = tid + j * 256;
                int row = cid >> 2, c16 = cid & 3;
                cp16(sb + h * A_BYTES + (uint32_t)(row * AROW + c16 * 8) * 2,
                     (const char*)(gA[h] + (size_t)row * K + ko) + c16 * 16);
            }
            #pragma unroll
            for (int j = 0; j < 2; j++) {          // B: 512 chunks
                int cid = tid + j * 256;
                int row = cid >> 2, c16 = cid & 3;
                cp16(sb + 2 * A_BYTES + h * B_BYTES +
                         (uint32_t)(row * AROW + c16 * 8) * 2,
                     (const char*)(gB[h] + (size_t)row * K + ko) + c16 * 16);
            }
        }
        cp_commit();
    };

    load_stage(0);
    load_stage(1);

    float acc[4][8][4];
    #pragma unroll
    for (int i = 0; i < 4; i++)
        #pragma unroll
        for (int j = 0; j < 8; j++)
            #pragma unroll
            for (int q = 0; q < 4; q++) acc[i][j][q] = 0.f;

    const int lrowA = lane & 15, lcolA = (lane >> 4) * 8;
    const int lrowB = (lane & 7) + ((lane >> 4) << 3);
    const int lcolB = ((lane >> 3) & 1) * 8;

    for (int t = 0; t < KT; t++) {
        cp_wait1();
        __syncthreads();
        if (t + 2 < KT) load_stage(t + 2);

        uint32_t sb  = sbase + (uint32_t)(t % STAGES) * STG_BYTES;
        uint32_t sAh = sb, sAl = sb + A_BYTES;
        uint32_t sBh = sb + 2 * A_BYTES, sBl = sBh + B_BYTES;

        #pragma unroll
        for (int kk = 0; kk < BK; kk += 16) {
            uint32_t aH[4][4], aL[4][4], bH[8][2], bL[8][2];
            #pragma unroll
            for (int mi = 0; mi < 4; mi++) {
                uint32_t off =
                    (uint32_t)((wm * 64 + mi * 16 + lrowA) * AROW + kk + lcolA) * 2;
                ldsm4(aH[mi], sAh + off);
                ldsm4(aL[mi], sAl + off);
            }
            #pragma unroll
            for (int np = 0; np < 4; np++) {
                uint32_t off =
                    (uint32_t)((wn * 64 + np * 16 + lrowB) * AROW + kk + lcolB) * 2;
                uint32_t r[4];
                ldsm4(r, sBh + off);
                bH[2 * np][0] = r[0]; bH[2 * np][1] = r[1];
                bH[2 * np + 1][0] = r[2]; bH[2 * np + 1][1] = r[3];
                ldsm4(r, sBl + off);
                bL[2 * np][0] = r[0]; bL[2 * np][1] = r[1];
                bL[2 * np + 1][0] = r[2]; bL[2 * np + 1][1] = r[3];
            }
            #pragma unroll
            for (int mi = 0; mi < 4; mi++)
                #pragma unroll
                for (int ni = 0; ni < 8; ni++) {
                    MMA(acc[mi][ni], aH[mi], bH[ni]);
                    MMA(acc[mi][ni], aH[mi], bL[ni]);
                    MMA(acc[mi][ni], aL[mi], bH[ni]);
                }
        }
    }

    // epilogue: registers -> GMEM (float2), fused bias/relu
    const int g = lane >> 2, tq = (lane & 3) * 2;
    const int crow = blockIdx.y * BM + wm * 64;
    const int ccol = blockIdx.x * BN + wn * 64;
    #pragma unroll
    for (int mi = 0; mi < 4; mi++) {
        #pragma unroll
        for (int ni = 0; ni < 8; ni++) {
            int row = crow + mi * 16 + g;
            int col = ccol + ni * 8 + tq;
            float2 v0 = make_float2(acc[mi][ni][0], acc[mi][ni][1]);
            float2 v1 = make_float2(acc[mi][ni][2], acc[mi][ni][3]);
            if (bias) {
                float2 bv = *(const float2*)(bias + col);
                v0.x += bv.x; v0.y += bv.y; v1.x += bv.x; v1.y += bv.y;
            }
            if (relu) {
                v0.x = fmaxf(v0.x, 0.f); v0.y = fmaxf(v0.y, 0.f);
                v1.x = fmaxf(v1.x, 0.f); v1.y = fmaxf(v1.y, 0.f);
            }
            *(float2*)&C[(size_t)row * N + col]       = v0;
            *(float2*)&C[(size_t)(row + 8) * N + col] = v1;
        }
    }
}

// ---------------------------------------------------------------------------
// LayerNorm (R4 version: fp32 out)
// ---------------------------------------------------------------------------
__global__ __launch_bounds__(256) void ln_kernel(
    const float* __restrict__ x, const float* __restrict__ g,
    const float* __restrict__ b, float* __restrict__ out)
{
    int row = blockIdx.x;
    const float* xr = x + (size_t)row * D_;
    float s = 0.f, s2 = 0.f;
    #pragma unroll
    for (int i = threadIdx.x; i < D_; i += 256) {
        float v = xr[i]; s += v; s2 += v * v;
    }
    __shared__ float sh[20];
    #pragma unroll
    for (int o = 16; o > 0; o >>= 1) {
        s  += __shfl_down_sync(0xffffffffu, s,  o);
        s2 += __shfl_down_sync(0xffffffffu, s2, o);
    }
    int warp = threadIdx.x >> 5, lane = threadIdx.x & 31;
    if (lane == 0) { sh[warp] = s; sh[warp + 8] = s2; }
    __syncthreads();
    if (threadIdx.x == 0) {
        float ts = 0.f, ts2 = 0.f;
        #pragma unroll
        for (int w = 0; w < 8; w++) { ts += sh[w]; ts2 += sh[w + 8]; }
        float mean = ts * (1.0f / D_);
        float var  = ts2 * (1.0f / D_) - mean * mean;
        sh[16] = mean;
        sh[17] = rsqrtf(var + 1e-5f);
    }
    __syncthreads();
    float mean = sh[16], inv = sh[17];
    float* orow = out + (size_t)row * D_;
    #pragma unroll
    for (int i = threadIdx.x; i < D_; i += 256)
        orow[i] = (xr[i] - mean) * inv * g[i] + b[i];
}

// ---------------------------------------------------------------------------
// Causal flash attention (R4 version); qkv packed [M, 3072] (row = t*B + b)
// ---------------------------------------------------------------------------
#define QKV_S 3072
__global__ __launch_bounds__(128) void attn_kernel(
    const float* __restrict__ qkv, float* __restrict__ o)
{
    __shared__ float Ks[64][64];
    __shared__ float Vs[64][64];
    const int bh = blockIdx.y;
    const int bb = bh >> 4, hh = bh & 15;            // batch, head
    const int i  = blockIdx.x * 128 + threadIdx.x;   // query time index
    const size_t colq = (size_t)hh * DH_;

    float qr[DH_];
    #pragma unroll
    for (int d = 0; d < DH_; d++)
        qr[d] = qkv[(size_t)(i * B_ + bb) * QKV_S + colq + d] * SCALE_;

    float m = -INFINITY, l = 0.f;
    float acc[DH_];
    #pragma unroll
    for (int d = 0; d < DH_; d++) acc[d] = 0.f;

    const int jend = blockIdx.x * 128 + 127;
    const int jr = threadIdx.x >> 1;
    const int c0 = (threadIdx.x & 1) * 32;

    for (int j0 = 0; j0 <= jend; j0 += 64) {
        const size_t gro = (size_t)((j0 + jr) * B_ + bb) * QKV_S + colq + c0;
        #pragma unroll
        for (int c = 0; c < 32; c += 4) {
            *(float4*)&Ks[jr][c0 + c] = *(const float4*)&qkv[gro + 1024 + c];
            *(float4*)&Vs[jr][c0 + c] = *(const float4*)&qkv[gro + 2048 + c];
        }
        __syncthreads();
        int jn = i - j0 + 1;
        if (jn > 64) jn = 64;
        for (int jj = 0; jj < jn; jj++) {
            float s = 0.f;
            #pragma unroll
            for (int d = 0; d < DH_; d++) s = fmaf(qr[d], Ks[jj][d], s);
            float mn   = fmaxf(m, s);
            float corr = __expf(m - mn);
            float p    = __expf(s - mn);
            l = l * corr + p;
            #pragma unroll
            for (int d = 0; d < DH_; d++)
                acc[d] = fmaf(acc[d], corr, p * Vs[jj][d]);
            m = mn;
        }
        __syncthreads();
    }
    float invl = 1.0f / l;
    float* ob = o + (size_t)(i * B_ + bb) * (H_ * DH_) + colq;
    #pragma unroll
    for (int d = 0; d < DH_; d++) ob[d] = acc[d] * invl;
}

// ---------------------------------------------------------------------------
// GRU gate: yW/xU packed [M, 3072] (r|z|g per row)
// ---------------------------------------------------------------------------
__global__ __launch_bounds__(256) void gru_kernel(
    const float* __restrict__ x,
    const float* __restrict__ yW, const float* __restrict__ xU,
    const float* __restrict__ bz, float* __restrict__ out)
{
    int idx = blockIdx.x * 256 + threadIdx.x;
    int row = idx >> 10, d = idx & (D_ - 1);
    size_t b = (size_t)row * 3072 + d;
    float r = 1.0f / (1.0f + expf(-(yW[b] + xU[b])));
    float z = 1.0f / (1.0f + expf(-(yW[b + 1024] + xU[b + 1024] + bz[d] - BG_)));
    float h = tanhf(yW[b + 2048] + r * xU[b + 2048]);
    out[idx] = (1.0f - z) * x[idx] + z * h;
}

// ---------------------------------------------------------------------------
static void conv_A(const float* src, __nv_bfloat16* ah, __nv_bfloat16* al, size_t n) {
    int n4 = (int)(n >> 2);
    splitA_kernel<<<(n4 + 255) / 256, 256>>>(src, ah, al, n4);
}
static void conv_B(const float* w, __nv_bfloat16* bh, __nv_bfloat16* bl, int K, int N,
                   size_t outRowOff) {
    dim3 g(N / 32, K / 32), b(32, 8);
    transB_kernel<<<g, b>>>(w, bh + outRowOff * K, bl + outRowOff * K, K, N);
}

extern "C" void kernel_launch(void* const* d_in, const int* in_sizes, int n_in,
                              void* d_out, int out_size)
{
    const float* x     = (const float*)d_in[0];
    const float* Wq    = (const float*)d_in[1];
    const float* Wk    = (const float*)d_in[2];
    const float* Wv    = (const float*)d_in[3];
    const float* Wo    = (const float*)d_in[4];
    const float* ln1_g = (const float*)d_in[5];
    const float* ln1_b = (const float*)d_in[6];
    const float* W1    = (const float*)d_in[7];
    const float* b1    = (const float*)d_in[8];
    const float* W2    = (const float*)d_in[9];
    const float* b2    = (const float*)d_in[10];
    const float* ln2_g = (const float*)d_in[11];
    const float* ln2_b = (const float*)d_in[12];
    const float* g1W   = (const float*)d_in[13];
    const float* g1U   = (const float*)d_in[14];
    const float* g1bz  = (const float*)d_in[15];
    const float* g2W   = (const float*)d_in[16];
    const float* g2U   = (const float*)d_in[17];
    const float* g2bz  = (const float*)d_in[18];
    float* out = (float*)d_out;

    float* buf = nullptr;
    __nv_bfloat16 *Ah, *Al, *Bh, *Bl;
    cudaGetSymbolAddress((void**)&buf, g_buf);
    cudaGetSymbolAddress((void**)&Ah, g_Ah);
    cudaGetSymbolAddress((void**)&Al, g_Al);
    cudaGetSymbolAddress((void**)&Bh, g_Bh);
    cudaGetSymbolAddress((void**)&Bl, g_Bl);

    float* xn    = buf + 0ull  * MD_;
    float* qkv   = buf + 1ull  * MD_;   // [M, 3072]
    float* attnb = buf + 4ull  * MD_;
    float* y     = buf + 5ull  * MD_;
    float* yW    = buf + 6ull  * MD_;   // [M, 3072]
    float* xU    = buf + 9ull  * MD_;   // [M, 3072]
    float* src   = buf + 12ull * MD_;
    float* sn    = buf + 13ull * MD_;
    float* ffo   = buf + 14ull * MD_;
    float* ff1   = buf + 15ull * MD_;   // [M, 4096]

    cudaFuncSetAttribute(mma_gemm, cudaFuncAttributeMaxDynamicSharedMemorySize,
                         GEMM_SMEM);

    const size_t DD = (size_t)D_ * D_;
    const dim3 g3(3072 / BN, M_ / BM);    // (24, 32)
    const dim3 g1k(1024 / BN, M_ / BM);   // (8, 32)
    const dim3 g4k(4096 / BN, M_ / BM);   // (32, 32)

    // --- LN1 + QKV (fused N=3072) ---
    ln_kernel<<<M_, 256>>>(x, ln1_g, ln1_b, xn);
    conv_A(xn, Ah, Al, (size_t)MD_);
    conv_B(Wq, Bh, Bl, D_, D_, 0);
    conv_B(Wk, Bh, Bl, D_, D_, 1024);
    conv_B(Wv, Bh, Bl, D_, D_, 2048);
    mma_gemm<<<g3, 256, GEMM_SMEM>>>(Ah, Al, Bh, Bl, qkv, M_, 3072, D_, nullptr, 0);

    // --- attention ---
    attn_kernel<<<dim3(T_ / 128, B_ * H_), 128>>>(qkv, attnb);

    // --- output projection ---
    conv_A(attnb, Ah, Al, (size_t)MD_);
    conv_B(Wo, Bh, Bl, D_, D_, 0);
    mma_gemm<<<g1k, 256, GEMM_SMEM>>>(Ah, Al, Bh, Bl, y, M_, 1024, D_, nullptr, 0);

    // --- GRU gate 1 ---
    conv_A(y, Ah, Al, (size_t)MD_);
    for (int i = 0; i < 3; i++) conv_B(g1W + i * DD, Bh, Bl, D_, D_, (size_t)i * 1024);
    mma_gemm<<<g3, 256, GEMM_SMEM>>>(Ah, Al, Bh, Bl, yW, M_, 3072, D_, nullptr, 0);
    conv_A(x, Ah, Al, (size_t)MD_);
    for (int i = 0; i < 3; i++) conv_B(g1U + i * DD, Bh, Bl, D_, D_, (size_t)i * 1024);
    mma_gemm<<<g3, 256, GEMM_SMEM>>>(Ah, Al, Bh, Bl, xU, M_, 3072, D_, nullptr, 0);
    gru_kernel<<<MD_ / 256, 256>>>(x, yW, xU, g1bz, src);

    // --- LN2 + FFN ---
    ln_kernel<<<M_, 256>>>(src, ln2_g, ln2_b, sn);
    conv_A(sn, Ah, Al, (size_t)MD_);
    conv_B(W1, Bh, Bl, D_, FF_, 0);
    mma_gemm<<<g4k, 256, GEMM_SMEM>>>(Ah, Al, Bh, Bl, ff1, M_, 4096, D_, b1, 1);
    conv_A(ff1, Ah, Al, (size_t)M_ * FF_);
    conv_B(W2, Bh, Bl, FF_, D_, 0);
    mma_gemm<<<g1k, 256, GEMM_SMEM>>>(Ah, Al, Bh, Bl, ffo, M_, 1024, FF_, b2, 0);

    // --- GRU gate 2 ---
    conv_A(ffo, Ah, Al, (size_t)MD_);
    for (int i = 0; i < 3; i++) conv_B(g2W + i * DD, Bh, Bl, D_, D_, (size_t)i * 1024);
    mma_gemm<<<g3, 256, GEMM_SMEM>>>(Ah, Al, Bh, Bl, yW, M_, 3072, D_, nullptr, 0);
    conv_A(src, Ah, Al, (size_t)MD_);
    for (int i = 0; i < 3; i++) conv_B(g2U + i * DD, Bh, Bl, D_, D_, (size_t)i * 1024);
    mma_gemm<<<g3, 256, GEMM_SMEM>>>(Ah, Al, Bh, Bl, xU, M_, 3072, D_, nullptr, 0);
    gru_kernel<<<MD_ / 256, 256>>>(src, yW, xU, g2bz, out);
}

// round 12
// speedup vs baseline: 1.4950x; 1.3207x over previous
#include <cuda_runtime.h>
#include <cuda_fp16.h>
#include <math.h>
#include <stdint.h>

// Problem constants
#define T_   1024
#define B_   8
#define D_   1024
#define H_   16
#define DH_  64
#define FF_  4096
#define M_   (T_ * B_)          // 8192
#define MD_  (8388608)          // M_ * D_
#define SCALE_ 0.125f
#define BG_  0.1f

// fp32 scratch:
// 0:xn 1-3:qkv 4:attnb 5:y 6-8:yW 9-11:xU 12:src 13:sn 14:ffo 15-18:ff1
__device__ float g_buf[19ull * 8388608ull];
// fp16 operand scratch
__device__ __half g_Ah[33554432];        // A (rounded to fp16), up to M x FF
__device__ __half g_Bh[4194304];         // B hi, up to 4096x1024 (as [N,K])
__device__ __half g_Bl[4194304];         // B lo

// ---------------------------------------------------------------------------
// PTX helpers
// ---------------------------------------------------------------------------
__device__ __forceinline__ uint32_t smem_u32(const void* p) {
    uint32_t a;
    asm("{ .reg .u64 t; cvta.to.shared.u64 t, %1; cvt.u32.u64 %0, t; }"
        : "=r"(a) : "l"(p));
    return a;
}
__device__ __forceinline__ void cp16(uint32_t s, const void* g) {
    asm volatile("cp.async.cg.shared.global [%0], [%1], 16;" :: "r"(s), "l"(g));
}
__device__ __forceinline__ void cp_commit() {
    asm volatile("cp.async.commit_group;" ::: "memory");
}
__device__ __forceinline__ void cp_wait1() {
    asm volatile("cp.async.wait_group 1;" ::: "memory");
}
__device__ __forceinline__ void ldsm4(uint32_t (&r)[4], uint32_t addr) {
    asm volatile("ldmatrix.sync.aligned.m8n8.x4.shared.b16 {%0,%1,%2,%3}, [%4];"
        : "=r"(r[0]), "=r"(r[1]), "=r"(r[2]), "=r"(r[3]) : "r"(addr));
}
// fp16 MMA, fp32 accumulate
#define MMA(d, a, b) \
    asm volatile("mma.sync.aligned.m16n8k16.row.col.f32.f16.f16.f32 " \
        "{%0,%1,%2,%3}, {%4,%5,%6,%7}, {%8,%9}, {%0,%1,%2,%3};" \
        : "+f"((d)[0]), "+f"((d)[1]), "+f"((d)[2]), "+f"((d)[3]) \
        : "r"((a)[0]), "r"((a)[1]), "r"((a)[2]), "r"((a)[3]), \
          "r"((b)[0]), "r"((b)[1]))

__device__ __forceinline__ void splitH(float v, __half& h, __half& l) {
    h = __float2half_rn(v);
    l = __float2half_rn(v - __half2float(h));
}

// ---------------------------------------------------------------------------
// fp32 -> fp16 convert (A operand; residual intentionally dropped)
// ---------------------------------------------------------------------------
__global__ __launch_bounds__(256) void convA_kernel(
    const float* __restrict__ in, __half* __restrict__ oh, int n4)
{
    int i = blockIdx.x * 256 + threadIdx.x;
    if (i >= n4) return;
    float4 v = ((const float4*)in)[i];
    __half2 a = __half2(__float2half_rn(v.x), __float2half_rn(v.y));
    __half2 b = __half2(__float2half_rn(v.z), __float2half_rn(v.w));
    ((__half2*)oh)[2 * i]     = a;
    ((__half2*)oh)[2 * i + 1] = b;
}

// ---------------------------------------------------------------------------
// Weight transpose + fp16 hi/lo split: fp32 [K,N] -> fp16 [N,K] hi + lo
// ---------------------------------------------------------------------------
__global__ __launch_bounds__(256) void transB_kernel(
    const float* __restrict__ in, __half* __restrict__ oh,
    __half* __restrict__ ol, int Kd, int Nd)
{
    __shared__ float t[32][33];
    int n0 = blockIdx.x * 32, k0 = blockIdx.y * 32;
    int tx = threadIdx.x, ty = threadIdx.y;      // (32, 8)
    #pragma unroll
    for (int j = 0; j < 32; j += 8)
        t[ty + j][tx] = in[(size_t)(k0 + ty + j) * Nd + n0 + tx];
    __syncthreads();
    #pragma unroll
    for (int j = 0; j < 32; j += 8) {
        __half h, l;
        splitH(t[tx][ty + j], h, l);
        size_t o = (size_t)(n0 + ty + j) * Kd + k0 + tx;
        oh[o] = h; ol[o] = l;
    }
}

// ---------------------------------------------------------------------------
// fp16 2-product GEMM: C[M,N] = A[M,K] @ (Bh+Bl)[N,K]^T
// CTA 256x128x32, 8 warps (64x64 each), 3-stage cp.async, 1 barrier/K-tile.
// ---------------------------------------------------------------------------
#define BM 256
#define BN 128
#define BK 32
#define STAGES 3
#define AROW 40                                // padded row stride (fp16)
#define A_BYTES (BM * AROW * 2)                // 20480
#define B_BYTES (BN * AROW * 2)                // 10240
#define STG_BYTES (A_BYTES + 2 * B_BYTES)      // 40960
#define GEMM_SMEM (STAGES * STG_BYTES)         // 122880

__global__ __launch_bounds__(256) void mma_gemm(
    const __half* __restrict__ Ah,
    const __half* __restrict__ Bh, const __half* __restrict__ Bl,
    float* __restrict__ C, int M, int N, int K,
    const float* __restrict__ bias, int relu)
{
    extern __shared__ char smem[];
    const uint32_t sbase = smem_u32(smem);
    const int tid = threadIdx.x, wid = tid >> 5, lane = tid & 31;
    const int wm = wid & 3, wn = wid >> 2;          // warp tile 64m x 64n
    const size_t arow0 = (size_t)blockIdx.y * BM;
    const size_t brow0 = (size_t)blockIdx.x * BN;
    const __half* gA = Ah + arow0 * K;
    const __half* gB[2] = { Bh + brow0 * K, Bl + brow0 * K };
    const int KT = K / BK;

    auto load_stage = [&](int t) {
        uint32_t sb = sbase + (uint32_t)(t % STAGES) * STG_BYTES;
        size_t ko = (size_t)t * BK;
        #pragma unroll
        for (int j = 0; j < 4; j++) {              // A: 1024 16B-chunks
            int cid = tid + j * 256;
            int row = cid >> 2, c16 = cid & 3;
            cp16(sb + (uint32_t)(row * AROW + c16 * 8) * 2,
                 (const char*)(gA + (size_t)row * K + ko) + c16 * 16);
        }
        #pragma unroll
        for (int h = 0; h < 2; h++) {
            #pragma unroll
            for (int j = 0; j < 2; j++) {          // B hi/lo: 512 chunks each
                int cid = tid + j * 256;
                int row = cid >> 2, c16 = cid & 3;
                cp16(sb + A_BYTES + h * B_BYTES +
                         (uint32_t)(row * AROW + c16 * 8) * 2,
                     (const char*)(gB[h] + (size_t)row * K + ko) + c16 * 16);
            }
        }
        cp_commit();
    };

    load_stage(0);
    load_stage(1);

    float acc[4][8][4];
    #pragma unroll
    for (int i = 0; i < 4; i++)
        #pragma unroll
        for (int j = 0; j < 8; j++)
            #pragma unroll
            for (int q = 0; q < 4; q++) acc[i][j][q] = 0.f;

    const int lrowA = lane & 15, lcolA = (lane >> 4) * 8;
    const int lrowB = (lane & 7) + ((lane >> 4) << 3);
    const int lcolB = ((lane >> 3) & 1) * 8;

    for (int t = 0; t < KT; t++) {
        cp_wait1();
        __syncthreads();
        if (t + 2 < KT) load_stage(t + 2);

        uint32_t sb  = sbase + (uint32_t)(t % STAGES) * STG_BYTES;
        uint32_t sA  = sb;
        uint32_t sBh = sb + A_BYTES, sBl = sBh + B_BYTES;

        #pragma unroll
        for (int kk = 0; kk < BK; kk += 16) {
            uint32_t aH[4][4], bH[8][2], bL[8][2];
            #pragma unroll
            for (int mi = 0; mi < 4; mi++) {
                uint32_t off =
                    (uint32_t)((wm * 64 + mi * 16 + lrowA) * AROW + kk + lcolA) * 2;
                ldsm4(aH[mi], sA + off);
            }
            #pragma unroll
            for (int np = 0; np < 4; np++) {
                uint32_t off =
                    (uint32_t)((wn * 64 + np * 16 + lrowB) * AROW + kk + lcolB) * 2;
                uint32_t r[4];
                ldsm4(r, sBh + off);
                bH[2 * np][0] = r[0]; bH[2 * np][1] = r[1];
                bH[2 * np + 1][0] = r[2]; bH[2 * np + 1][1] = r[3];
                ldsm4(r, sBl + off);
                bL[2 * np][0] = r[0]; bL[2 * np][1] = r[1];
                bL[2 * np + 1][0] = r[2]; bL[2 * np + 1][1] = r[3];
            }
            #pragma unroll
            for (int mi = 0; mi < 4; mi++)
                #pragma unroll
                for (int ni = 0; ni < 8; ni++) {
                    MMA(acc[mi][ni], aH[mi], bH[ni]);
                    MMA(acc[mi][ni], aH[mi], bL[ni]);
                }
        }
    }

    // epilogue: registers -> GMEM (float2), fused bias/relu
    const int g = lane >> 2, tq = (lane & 3) * 2;
    const int crow = blockIdx.y * BM + wm * 64;
    const int ccol = blockIdx.x * BN + wn * 64;
    #pragma unroll
    for (int mi = 0; mi < 4; mi++) {
        #pragma unroll
        for (int ni = 0; ni < 8; ni++) {
            int row = crow + mi * 16 + g;
            int col = ccol + ni * 8 + tq;
            float2 v0 = make_float2(acc[mi][ni][0], acc[mi][ni][1]);
            float2 v1 = make_float2(acc[mi][ni][2], acc[mi][ni][3]);
            if (bias) {
                float2 bv = *(const float2*)(bias + col);
                v0.x += bv.x; v0.y += bv.y; v1.x += bv.x; v1.y += bv.y;
            }
            if (relu) {
                v0.x = fmaxf(v0.x, 0.f); v0.y = fmaxf(v0.y, 0.f);
                v1.x = fmaxf(v1.x, 0.f); v1.y = fmaxf(v1.y, 0.f);
            }
            *(float2*)&C[(size_t)row * N + col]       = v0;
            *(float2*)&C[(size_t)(row + 8) * N + col] = v1;
        }
    }
}

// ---------------------------------------------------------------------------
// LayerNorm (fp32 out)
// ---------------------------------------------------------------------------
__global__ __launch_bounds__(256) void ln_kernel(
    const float* __restrict__ x, const float* __restrict__ g,
    const float* __restrict__ b, float* __restrict__ out)
{
    int row = blockIdx.x;
    const float* xr = x + (size_t)row * D_;
    float s = 0.f, s2 = 0.f;
    #pragma unroll
    for (int i = threadIdx.x; i < D_; i += 256) {
        float v = xr[i]; s += v; s2 += v * v;
    }
    __shared__ float sh[20];
    #pragma unroll
    for (int o = 16; o > 0; o >>= 1) {
        s  += __shfl_down_sync(0xffffffffu, s,  o);
        s2 += __shfl_down_sync(0xffffffffu, s2, o);
    }
    int warp = threadIdx.x >> 5, lane = threadIdx.x & 31;
    if (lane == 0) { sh[warp] = s; sh[warp + 8] = s2; }
    __syncthreads();
    if (threadIdx.x == 0) {
        float ts = 0.f, ts2 = 0.f;
        #pragma unroll
        for (int w = 0; w < 8; w++) { ts += sh[w]; ts2 += sh[w + 8]; }
        float mean = ts * (1.0f / D_);
        float var  = ts2 * (1.0f / D_) - mean * mean;
        sh[16] = mean;
        sh[17] = rsqrtf(var + 1e-5f);
    }
    __syncthreads();
    float mean = sh[16], inv = sh[17];
    float* orow = out + (size_t)row * D_;
    #pragma unroll
    for (int i = threadIdx.x; i < D_; i += 256)
        orow[i] = (xr[i] - mean) * inv * g[i] + b[i];
}

// ---------------------------------------------------------------------------
// Causal flash attention; qkv packed [M, 3072] (row = t*B + b)
// ---------------------------------------------------------------------------
#define QKV_S 3072
__global__ __launch_bounds__(128) void attn_kernel(
    const float* __restrict__ qkv, float* __restrict__ o)
{
    __shared__ float Ks[64][64];
    __shared__ float Vs[64][64];
    const int bh = blockIdx.y;
    const int bb = bh >> 4, hh = bh & 15;            // batch, head
    const int i  = blockIdx.x * 128 + threadIdx.x;   // query time index
    const size_t colq = (size_t)hh * DH_;

    float qr[DH_];
    #pragma unroll
    for (int d = 0; d < DH_; d++)
        qr[d] = qkv[(size_t)(i * B_ + bb) * QKV_S + colq + d] * SCALE_;

    float m = -INFINITY, l = 0.f;
    float acc[DH_];
    #pragma unroll
    for (int d = 0; d < DH_; d++) acc[d] = 0.f;

    const int jend = blockIdx.x * 128 + 127;
    const int jr = threadIdx.x >> 1;
    const int c0 = (threadIdx.x & 1) * 32;

    for (int j0 = 0; j0 <= jend; j0 += 64) {
        const size_t gro = (size_t)((j0 + jr) * B_ + bb) * QKV_S + colq + c0;
        #pragma unroll
        for (int c = 0; c < 32; c += 4) {
            *(float4*)&Ks[jr][c0 + c] = *(const float4*)&qkv[gro + 1024 + c];
            *(float4*)&Vs[jr][c0 + c] = *(const float4*)&qkv[gro + 2048 + c];
        }
        __syncthreads();
        int jn = i - j0 + 1;
        if (jn > 64) jn = 64;
        for (int jj = 0; jj < jn; jj++) {
            float s = 0.f;
            #pragma unroll
            for (int d = 0; d < DH_; d++) s = fmaf(qr[d], Ks[jj][d], s);
            float mn   = fmaxf(m, s);
            float corr = __expf(m - mn);
            float p    = __expf(s - mn);
            l = l * corr + p;
            #pragma unroll
            for (int d = 0; d < DH_; d++)
                acc[d] = fmaf(acc[d], corr, p * Vs[jj][d]);
            m = mn;
        }
        __syncthreads();
    }
    float invl = 1.0f / l;
    float* ob = o + (size_t)(i * B_ + bb) * (H_ * DH_) + colq;
    #pragma unroll
    for (int d = 0; d < DH_; d++) ob[d] = acc[d] * invl;
}

// ---------------------------------------------------------------------------
// GRU gate: yW/xU packed [M, 3072] (r|z|g per row)
// ---------------------------------------------------------------------------
__global__ __launch_bounds__(256) void gru_kernel(
    const float* __restrict__ x,
    const float* __restrict__ yW, const float* __restrict__ xU,
    const float* __restrict__ bz, float* __restrict__ out)
{
    int idx = blockIdx.x * 256 + threadIdx.x;
    int row = idx >> 10, d = idx & (D_ - 1);
    size_t b = (size_t)row * 3072 + d;
    float r = 1.0f / (1.0f + expf(-(yW[b] + xU[b])));
    float z = 1.0f / (1.0f + expf(-(yW[b + 1024] + xU[b + 1024] + bz[d] - BG_)));
    float h = tanhf(yW[b + 2048] + r * xU[b + 2048]);
    out[idx] = (1.0f - z) * x[idx] + z * h;
}

// ---------------------------------------------------------------------------
static void conv_A(const float* src, __half* ah, size_t n) {
    int n4 = (int)(n >> 2);
    convA_kernel<<<(n4 + 255) / 256, 256>>>(src, ah, n4);
}
static void conv_B(const float* w, __half* bh, __half* bl, int K, int N,
                   size_t outRowOff) {
    dim3 g(N / 32, K / 32), b(32, 8);
    transB_kernel<<<g, b>>>(w, bh + outRowOff * K, bl + outRowOff * K, K, N);
}

extern "C" void kernel_launch(void* const* d_in, const int* in_sizes, int n_in,
                              void* d_out, int out_size)
{
    const float* x     = (const float*)d_in[0];
    const float* Wq    = (const float*)d_in[1];
    const float* Wk    = (const float*)d_in[2];
    const float* Wv    = (const float*)d_in[3];
    const float* Wo    = (const float*)d_in[4];
    const float* ln1_g = (const float*)d_in[5];
    const float* ln1_b = (const float*)d_in[6];
    const float* W1    = (const float*)d_in[7];
    const float* b1    = (const float*)d_in[8];
    const float* W2    = (const float*)d_in[9];
    const float* b2    = (const float*)d_in[10];
    const float* ln2_g = (const float*)d_in[11];
    const float* ln2_b = (const float*)d_in[12];
    const float* g1W   = (const float*)d_in[13];
    const float* g1U   = (const float*)d_in[14];
    const float* g1bz  = (const float*)d_in[15];
    const float* g2W   = (const float*)d_in[16];
    const float* g2U   = (const float*)d_in[17];
    const float* g2bz  = (const float*)d_in[18];
    float* out = (float*)d_out;

    float* buf = nullptr;
    __half *Ah, *Bh, *Bl;
    cudaGetSymbolAddress((void**)&buf, g_buf);
    cudaGetSymbolAddress((void**)&Ah, g_Ah);
    cudaGetSymbolAddress((void**)&Bh, g_Bh);
    cudaGetSymbolAddress((void**)&Bl, g_Bl);

    float* xn    = buf + 0ull  * MD_;
    float* qkv   = buf + 1ull  * MD_;   // [M, 3072]
    float* attnb = buf + 4ull  * MD_;
    float* y     = buf + 5ull  * MD_;
    float* yW    = buf + 6ull  * MD_;   // [M, 3072]
    float* xU    = buf + 9ull  * MD_;   // [M, 3072]
    float* src   = buf + 12ull * MD_;
    float* sn    = buf + 13ull * MD_;
    float* ffo   = buf + 14ull * MD_;
    float* ff1   = buf + 15ull * MD_;   // [M, 4096]

    cudaFuncSetAttribute(mma_gemm, cudaFuncAttributeMaxDynamicSharedMemorySize,
                         GEMM_SMEM);

    const size_t DD = (size_t)D_ * D_;
    const dim3 g3(3072 / BN, M_ / BM);    // (24, 32)
    const dim3 g1k(1024 / BN, M_ / BM);   // (8, 32)
    const dim3 g4k(4096 / BN, M_ / BM);   // (32, 32)

    // --- LN1 + QKV (fused N=3072) ---
    ln_kernel<<<M_, 256>>>(x, ln1_g, ln1_b, xn);
    conv_A(xn, Ah, (size_t)MD_);
    conv_B(Wq, Bh, Bl, D_, D_, 0);
    conv_B(Wk, Bh, Bl, D_, D_, 1024);
    conv_B(Wv, Bh, Bl, D_, D_, 2048);
    mma_gemm<<<g3, 256, GEMM_SMEM>>>(Ah, Bh, Bl, qkv, M_, 3072, D_, nullptr, 0);

    // --- attention ---
    attn_kernel<<<dim3(T_ / 128, B_ * H_), 128>>>(qkv, attnb);

    // --- output projection ---
    conv_A(attnb, Ah, (size_t)MD_);
    conv_B(Wo, Bh, Bl, D_, D_, 0);
    mma_gemm<<<g1k, 256, GEMM_SMEM>>>(Ah, Bh, Bl, y, M_, 1024, D_, nullptr, 0);

    // --- GRU gate 1 ---
    conv_A(y, Ah, (size_t)MD_);
    for (int i = 0; i < 3; i++) conv_B(g1W + i * DD, Bh, Bl, D_, D_, (size_t)i * 1024);
    mma_gemm<<<g3, 256, GEMM_SMEM>>>(Ah, Bh, Bl, yW, M_, 3072, D_, nullptr, 0);
    conv_A(x, Ah, (size_t)MD_);
    for (int i = 0; i < 3; i++) conv_B(g1U + i * DD, Bh, Bl, D_, D_, (size_t)i * 1024);
    mma_gemm<<<g3, 256, GEMM_SMEM>>>(Ah, Bh, Bl, xU, M_, 3072, D_, nullptr, 0);
    gru_kernel<<<MD_ / 256, 256>>>(x, yW, xU, g1bz, src);

    // --- LN2 + FFN ---
    ln_kernel<<<M_, 256>>>(src, ln2_g, ln2_b, sn);
    conv_A(sn, Ah, (size_t)MD_);
    conv_B(W1, Bh, Bl, D_, FF_, 0);
    mma_gemm<<<g4k, 256, GEMM_SMEM>>>(Ah, Bh, Bl, ff1, M_, 4096, D_, b1, 1);
    conv_A(ff1, Ah, (size_t)M_ * FF_);
    conv_B(W2, Bh, Bl, FF_, D_, 0);
    mma_gemm<<<g1k, 256, GEMM_SMEM>>>(Ah, Bh, Bl, ffo, M_, 1024, FF_, b2, 0);

    // --- GRU gate 2 ---
    conv_A(ffo, Ah, (size_t)MD_);
    for (int i = 0; i < 3; i++) conv_B(g2W + i * DD, Bh, Bl, D_, D_, (size_t)i * 1024);
    mma_gemm<<<g3, 256, GEMM_SMEM>>>(Ah, Bh, Bl, yW, M_, 3072, D_, nullptr, 0);
    conv_A(src, Ah, (size_t)MD_);
    for (int i = 0; i < 3; i++) conv_B(g2U + i * DD, Bh, Bl, D_, D_, (size_t)i * 1024);
    mma_gemm<<<g3, 256, GEMM_SMEM>>>(Ah, Bh, Bl, xU, M_, 3072, D_, nullptr, 0);
    gru_kernel<<<MD_ / 256, 256>>>(src, yW, xU, g2bz, out);
}

// round 13
// speedup vs baseline: 2.0313x; 1.3587x over previous
#include <cuda_runtime.h>
#include <cuda_fp16.h>
#include <math.h>
#include <stdint.h>

// Problem constants
#define T_   1024
#define B_   8
#define D_   1024
#define H_   16
#define DH_  64
#define FF_  4096
#define M_   (T_ * B_)          // 8192
#define MD_  (8388608)          // M_ * D_
#define SCALE_ 0.125f
#define BG_  0.1f

// fp32 scratch:
// 0:xn 1-3:qkv 4:attnb 5:y 6-8:yW 9-11:xU 12:src 13:sn 14:ffo 15-18:ff1
__device__ float g_buf[19ull * 8388608ull];
// fp16 operand scratch
__device__ __half g_Ah[33554432];        // A (rounded to fp16), up to M x FF
__device__ __half g_Bh[4194304];         // B (rounded to fp16), [N,K]

// ---------------------------------------------------------------------------
// PTX helpers
// ---------------------------------------------------------------------------
__device__ __forceinline__ uint32_t smem_u32(const void* p) {
    uint32_t a;
    asm("{ .reg .u64 t; cvta.to.shared.u64 t, %1; cvt.u32.u64 %0, t; }"
        : "=r"(a) : "l"(p));
    return a;
}
__device__ __forceinline__ void cp16(uint32_t s, const void* g) {
    asm volatile("cp.async.cg.shared.global [%0], [%1], 16;" :: "r"(s), "l"(g));
}
__device__ __forceinline__ void cp_commit() {
    asm volatile("cp.async.commit_group;" ::: "memory");
}
__device__ __forceinline__ void cp_wait1() {
    asm volatile("cp.async.wait_group 1;" ::: "memory");
}
__device__ __forceinline__ void ldsm4(uint32_t (&r)[4], uint32_t addr) {
    asm volatile("ldmatrix.sync.aligned.m8n8.x4.shared.b16 {%0,%1,%2,%3}, [%4];"
        : "=r"(r[0]), "=r"(r[1]), "=r"(r[2]), "=r"(r[3]) : "r"(addr));
}
// fp16 MMA, fp32 accumulate
#define MMA(d, a, b) \
    asm volatile("mma.sync.aligned.m16n8k16.row.col.f32.f16.f16.f32 " \
        "{%0,%1,%2,%3}, {%4,%5,%6,%7}, {%8,%9}, {%0,%1,%2,%3};" \
        : "+f"((d)[0]), "+f"((d)[1]), "+f"((d)[2]), "+f"((d)[3]) \
        : "r"((a)[0]), "r"((a)[1]), "r"((a)[2]), "r"((a)[3]), \
          "r"((b)[0]), "r"((b)[1]))

// ---------------------------------------------------------------------------
// fp32 -> fp16 convert (A operand)
// ---------------------------------------------------------------------------
__global__ __launch_bounds__(256) void convA_kernel(
    const float* __restrict__ in, __half* __restrict__ oh, int n4)
{
    int i = blockIdx.x * 256 + threadIdx.x;
    if (i >= n4) return;
    float4 v = ((const float4*)in)[i];
    __half2 a = __half2(__float2half_rn(v.x), __float2half_rn(v.y));
    __half2 b = __half2(__float2half_rn(v.z), __float2half_rn(v.w));
    ((__half2*)oh)[2 * i]     = a;
    ((__half2*)oh)[2 * i + 1] = b;
}

// ---------------------------------------------------------------------------
// Weight transpose + fp16 convert: fp32 [K,N] -> fp16 [N,K]
// ---------------------------------------------------------------------------
__global__ __launch_bounds__(256) void transB_kernel(
    const float* __restrict__ in, __half* __restrict__ oh, int Kd, int Nd)
{
    __shared__ float t[32][33];
    int n0 = blockIdx.x * 32, k0 = blockIdx.y * 32;
    int tx = threadIdx.x, ty = threadIdx.y;      // (32, 8)
    #pragma unroll
    for (int j = 0; j < 32; j += 8)
        t[ty + j][tx] = in[(size_t)(k0 + ty + j) * Nd + n0 + tx];
    __syncthreads();
    #pragma unroll
    for (int j = 0; j < 32; j += 8) {
        size_t o = (size_t)(n0 + ty + j) * Kd + k0 + tx;
        oh[o] = __float2half_rn(t[tx][ty + j]);
    }
}

// ---------------------------------------------------------------------------
// fp16 GEMM: C[M,N] = A[M,K] @ B[N,K]^T  (fp32 accumulate)
// CTA 256x128x32, 8 warps (64x64 each), 3-stage cp.async, 1 barrier/K-tile.
// ---------------------------------------------------------------------------
#define BM 256
#define BN 128
#define BK 32
#define STAGES 3
#define AROW 40                                // padded row stride (fp16)
#define A_BYTES (BM * AROW * 2)                // 20480
#define B_BYTES (BN * AROW * 2)                // 10240
#define STG_BYTES (A_BYTES + B_BYTES)          // 30720
#define GEMM_SMEM (STAGES * STG_BYTES)         // 92160

__global__ __launch_bounds__(256) void mma_gemm(
    const __half* __restrict__ Ah, const __half* __restrict__ Bh,
    float* __restrict__ C, int M, int N, int K,
    const float* __restrict__ bias, int relu)
{
    extern __shared__ char smem[];
    const uint32_t sbase = smem_u32(smem);
    const int tid = threadIdx.x, wid = tid >> 5, lane = tid & 31;
    const int wm = wid & 3, wn = wid >> 2;          // warp tile 64m x 64n
    const size_t arow0 = (size_t)blockIdx.y * BM;
    const size_t brow0 = (size_t)blockIdx.x * BN;
    const __half* gA = Ah + arow0 * K;
    const __half* gB = Bh + brow0 * K;
    const int KT = K / BK;

    auto load_stage = [&](int t) {
        uint32_t sb = sbase + (uint32_t)(t % STAGES) * STG_BYTES;
        size_t ko = (size_t)t * BK;
        #pragma unroll
        for (int j = 0; j < 4; j++) {              // A: 1024 16B-chunks
            int cid = tid + j * 256;
            int row = cid >> 2, c16 = cid & 3;
            cp16(sb + (uint32_t)(row * AROW + c16 * 8) * 2,
                 (const char*)(gA + (size_t)row * K + ko) + c16 * 16);
        }
        #pragma unroll
        for (int j = 0; j < 2; j++) {              // B: 512 chunks
            int cid = tid + j * 256;
            int row = cid >> 2, c16 = cid & 3;
            cp16(sb + A_BYTES + (uint32_t)(row * AROW + c16 * 8) * 2,
                 (const char*)(gB + (size_t)row * K + ko) + c16 * 16);
        }
        cp_commit();
    };

    load_stage(0);
    load_stage(1);

    float acc[4][8][4];
    #pragma unroll
    for (int i = 0; i < 4; i++)
        #pragma unroll
        for (int j = 0; j < 8; j++)
            #pragma unroll
            for (int q = 0; q < 4; q++) acc[i][j][q] = 0.f;

    const int lrowA = lane & 15, lcolA = (lane >> 4) * 8;
    const int lrowB = (lane & 7) + ((lane >> 4) << 3);
    const int lcolB = ((lane >> 3) & 1) * 8;

    for (int t = 0; t < KT; t++) {
        cp_wait1();
        __syncthreads();
        if (t + 2 < KT) load_stage(t + 2);

        uint32_t sb = sbase + (uint32_t)(t % STAGES) * STG_BYTES;
        uint32_t sA = sb, sB = sb + A_BYTES;

        #pragma unroll
        for (int kk = 0; kk < BK; kk += 16) {
            uint32_t aH[4][4], bH[8][2];
            #pragma unroll
            for (int mi = 0; mi < 4; mi++) {
                uint32_t off =
                    (uint32_t)((wm * 64 + mi * 16 + lrowA) * AROW + kk + lcolA) * 2;
                ldsm4(aH[mi], sA + off);
            }
            #pragma unroll
            for (int np = 0; np < 4; np++) {
                uint32_t off =
                    (uint32_t)((wn * 64 + np * 16 + lrowB) * AROW + kk + lcolB) * 2;
                uint32_t r[4];
                ldsm4(r, sB + off);
                bH[2 * np][0] = r[0]; bH[2 * np][1] = r[1];
                bH[2 * np + 1][0] = r[2]; bH[2 * np + 1][1] = r[3];
            }
            #pragma unroll
            for (int mi = 0; mi < 4; mi++)
                #pragma unroll
                for (int ni = 0; ni < 8; ni++)
                    MMA(acc[mi][ni], aH[mi], bH[ni]);
        }
    }

    // epilogue: registers -> GMEM (float2), fused bias/relu
    const int g = lane >> 2, tq = (lane & 3) * 2;
    const int crow = blockIdx.y * BM + wm * 64;
    const int ccol = blockIdx.x * BN + wn * 64;
    #pragma unroll
    for (int mi = 0; mi < 4; mi++) {
        #pragma unroll
        for (int ni = 0; ni < 8; ni++) {
            int row = crow + mi * 16 + g;
            int col = ccol + ni * 8 + tq;
            float2 v0 = make_float2(acc[mi][ni][0], acc[mi][ni][1]);
            float2 v1 = make_float2(acc[mi][ni][2], acc[mi][ni][3]);
            if (bias) {
                float2 bv = *(const float2*)(bias + col);
                v0.x += bv.x; v0.y += bv.y; v1.x += bv.x; v1.y += bv.y;
            }
            if (relu) {
                v0.x = fmaxf(v0.x, 0.f); v0.y = fmaxf(v0.y, 0.f);
                v1.x = fmaxf(v1.x, 0.f); v1.y = fmaxf(v1.y, 0.f);
            }
            *(float2*)&C[(size_t)row * N + col]       = v0;
            *(float2*)&C[(size_t)(row + 8) * N + col] = v1;
        }
    }
}

// ---------------------------------------------------------------------------
// LayerNorm (fp32 out)
// ---------------------------------------------------------------------------
__global__ __launch_bounds__(256) void ln_kernel(
    const float* __restrict__ x, const float* __restrict__ g,
    const float* __restrict__ b, float* __restrict__ out)
{
    int row = blockIdx.x;
    const float* xr = x + (size_t)row * D_;
    float s = 0.f, s2 = 0.f;
    #pragma unroll
    for (int i = threadIdx.x; i < D_; i += 256) {
        float v = xr[i]; s += v; s2 += v * v;
    }
    __shared__ float sh[20];
    #pragma unroll
    for (int o = 16; o > 0; o >>= 1) {
        s  += __shfl_down_sync(0xffffffffu, s,  o);
        s2 += __shfl_down_sync(0xffffffffu, s2, o);
    }
    int warp = threadIdx.x >> 5, lane = threadIdx.x & 31;
    if (lane == 0) { sh[warp] = s; sh[warp + 8] = s2; }
    __syncthreads();
    if (threadIdx.x == 0) {
        float ts = 0.f, ts2 = 0.f;
        #pragma unroll
        for (int w = 0; w < 8; w++) { ts += sh[w]; ts2 += sh[w + 8]; }
        float mean = ts * (1.0f / D_);
        float var  = ts2 * (1.0f / D_) - mean * mean;
        sh[16] = mean;
        sh[17] = rsqrtf(var + 1e-5f);
    }
    __syncthreads();
    float mean = sh[16], inv = sh[17];
    float* orow = out + (size_t)row * D_;
    #pragma unroll
    for (int i = threadIdx.x; i < D_; i += 256)
        orow[i] = (xr[i] - mean) * inv * g[i] + b[i];
}

// ---------------------------------------------------------------------------
// Causal flash attention; qkv packed [M, 3072] (row = t*B + b)
// ---------------------------------------------------------------------------
#define QKV_S 3072
__global__ __launch_bounds__(128) void attn_kernel(
    const float* __restrict__ qkv, float* __restrict__ o)
{
    __shared__ float Ks[64][64];
    __shared__ float Vs[64][64];
    const int bh = blockIdx.y;
    const int bb = bh >> 4, hh = bh & 15;            // batch, head
    const int i  = blockIdx.x * 128 + threadIdx.x;   // query time index
    const size_t colq = (size_t)hh * DH_;

    float qr[DH_];
    #pragma unroll
    for (int d = 0; d < DH_; d++)
        qr[d] = qkv[(size_t)(i * B_ + bb) * QKV_S + colq + d] * SCALE_;

    float m = -INFINITY, l = 0.f;
    float acc[DH_];
    #pragma unroll
    for (int d = 0; d < DH_; d++) acc[d] = 0.f;

    const int jend = blockIdx.x * 128 + 127;
    const int jr = threadIdx.x >> 1;
    const int c0 = (threadIdx.x & 1) * 32;

    for (int j0 = 0; j0 <= jend; j0 += 64) {
        const size_t gro = (size_t)((j0 + jr) * B_ + bb) * QKV_S + colq + c0;
        #pragma unroll
        for (int c = 0; c < 32; c += 4) {
            *(float4*)&Ks[jr][c0 + c] = *(const float4*)&qkv[gro + 1024 + c];
            *(float4*)&Vs[jr][c0 + c] = *(const float4*)&qkv[gro + 2048 + c];
        }
        __syncthreads();
        int jn = i - j0 + 1;
        if (jn > 64) jn = 64;
        for (int jj = 0; jj < jn; jj++) {
            float s = 0.f;
            #pragma unroll
            for (int d = 0; d < DH_; d++) s = fmaf(qr[d], Ks[jj][d], s);
            float mn   = fmaxf(m, s);
            float corr = __expf(m - mn);
            float p    = __expf(s - mn);
            l = l * corr + p;
            #pragma unroll
            for (int d = 0; d < DH_; d++)
                acc[d] = fmaf(acc[d], corr, p * Vs[jj][d]);
            m = mn;
        }
        __syncthreads();
    }
    float invl = 1.0f / l;
    float* ob = o + (size_t)(i * B_ + bb) * (H_ * DH_) + colq;
    #pragma unroll
    for (int d = 0; d < DH_; d++) ob[d] = acc[d] * invl;
}

// ---------------------------------------------------------------------------
// GRU gate: yW/xU packed [M, 3072] (r|z|g per row)
// ---------------------------------------------------------------------------
__global__ __launch_bounds__(256) void gru_kernel(
    const float* __restrict__ x,
    const float* __restrict__ yW, const float* __restrict__ xU,
    const float* __restrict__ bz, float* __restrict__ out)
{
    int idx = blockIdx.x * 256 + threadIdx.x;
    int row = idx >> 10, d = idx & (D_ - 1);
    size_t b = (size_t)row * 3072 + d;
    float r = 1.0f / (1.0f + expf(-(yW[b] + xU[b])));
    float z = 1.0f / (1.0f + expf(-(yW[b + 1024] + xU[b + 1024] + bz[d] - BG_)));
    float h = tanhf(yW[b + 2048] + r * xU[b + 2048]);
    out[idx] = (1.0f - z) * x[idx] + z * h;
}

// ---------------------------------------------------------------------------
static void conv_A(const float* src, __half* ah, size_t n) {
    int n4 = (int)(n >> 2);
    convA_kernel<<<(n4 + 255) / 256, 256>>>(src, ah, n4);
}
static void conv_B(const float* w, __half* bh, int K, int N, size_t outRowOff) {
    dim3 g(N / 32, K / 32), b(32, 8);
    transB_kernel<<<g, b>>>(w, bh + outRowOff * K, K, N);
}

extern "C" void kernel_launch(void* const* d_in, const int* in_sizes, int n_in,
                              void* d_out, int out_size)
{
    const float* x     = (const float*)d_in[0];
    const float* Wq    = (const float*)d_in[1];
    const float* Wk    = (const float*)d_in[2];
    const float* Wv    = (const float*)d_in[3];
    const float* Wo    = (const float*)d_in[4];
    const float* ln1_g = (const float*)d_in[5];
    const float* ln1_b = (const float*)d_in[6];
    const float* W1    = (const float*)d_in[7];
    const float* b1    = (const float*)d_in[8];
    const float* W2    = (const float*)d_in[9];
    const float* b2    = (const float*)d_in[10];
    const float* ln2_g = (const float*)d_in[11];
    const float* ln2_b = (const float*)d_in[12];
    const float* g1W   = (const float*)d_in[13];
    const float* g1U   = (const float*)d_in[14];
    const float* g1bz  = (const float*)d_in[15];
    const float* g2W   = (const float*)d_in[16];
    const float* g2U   = (const float*)d_in[17];
    const float* g2bz  = (const float*)d_in[18];
    float* out = (float*)d_out;

    float* buf = nullptr;
    __half *Ah, *Bh;
    cudaGetSymbolAddress((void**)&buf, g_buf);
    cudaGetSymbolAddress((void**)&Ah, g_Ah);
    cudaGetSymbolAddress((void**)&Bh, g_Bh);

    float* xn    = buf + 0ull  * MD_;
    float* qkv   = buf + 1ull  * MD_;   // [M, 3072]
    float* attnb = buf + 4ull  * MD_;
    float* y     = buf + 5ull  * MD_;
    float* yW    = buf + 6ull  * MD_;   // [M, 3072]
    float* xU    = buf + 9ull  * MD_;   // [M, 3072]
    float* src   = buf + 12ull * MD_;
    float* sn    = buf + 13ull * MD_;
    float* ffo   = buf + 14ull * MD_;
    float* ff1   = buf + 15ull * MD_;   // [M, 4096]

    cudaFuncSetAttribute(mma_gemm, cudaFuncAttributeMaxDynamicSharedMemorySize,
                         GEMM_SMEM);

    const size_t DD = (size_t)D_ * D_;
    const dim3 g3(3072 / BN, M_ / BM);    // (24, 32)
    const dim3 g1k(1024 / BN, M_ / BM);   // (8, 32)
    const dim3 g4k(4096 / BN, M_ / BM);   // (32, 32)

    // --- LN1 + QKV (fused N=3072) ---
    ln_kernel<<<M_, 256>>>(x, ln1_g, ln1_b, xn);
    conv_A(xn, Ah, (size_t)MD_);
    conv_B(Wq, Bh, D_, D_, 0);
    conv_B(Wk, Bh, D_, D_, 1024);
    conv_B(Wv, Bh, D_, D_, 2048);
    mma_gemm<<<g3, 256, GEMM_SMEM>>>(Ah, Bh, qkv, M_, 3072, D_, nullptr, 0);

    // --- attention ---
    attn_kernel<<<dim3(T_ / 128, B_ * H_), 128>>>(qkv, attnb);

    // --- output projection ---
    conv_A(attnb, Ah, (size_t)MD_);
    conv_B(Wo, Bh, D_, D_, 0);
    mma_gemm<<<g1k, 256, GEMM_SMEM>>>(Ah, Bh, y, M_, 1024, D_, nullptr, 0);

    // --- GRU gate 1 ---
    conv_A(y, Ah, (size_t)MD_);
    for (int i = 0; i < 3; i++) conv_B(g1W + i * DD, Bh, D_, D_, (size_t)i * 1024);
    mma_gemm<<<g3, 256, GEMM_SMEM>>>(Ah, Bh, yW, M_, 3072, D_, nullptr, 0);
    conv_A(x, Ah, (size_t)MD_);
    for (int i = 0; i < 3; i++) conv_B(g1U + i * DD, Bh, D_, D_, (size_t)i * 1024);
    mma_gemm<<<g3, 256, GEMM_SMEM>>>(Ah, Bh, xU, M_, 3072, D_, nullptr, 0);
    gru_kernel<<<MD_ / 256, 256>>>(x, yW, xU, g1bz, src);

    // --- LN2 + FFN ---
    ln_kernel<<<M_, 256>>>(src, ln2_g, ln2_b, sn);
    conv_A(sn, Ah, (size_t)MD_);
    conv_B(W1, Bh, D_, FF_, 0);
    mma_gemm<<<g4k, 256, GEMM_SMEM>>>(Ah, Bh, ff1, M_, 4096, D_, b1, 1);
    conv_A(ff1, Ah, (size_t)M_ * FF_);
    conv_B(W2, Bh, FF_, D_, 0);
    mma_gemm<<<g1k, 256, GEMM_SMEM>>>(Ah, Bh, ffo, M_, 1024, FF_, b2, 0);

    // --- GRU gate 2 ---
    conv_A(ffo, Ah, (size_t)MD_);
    for (int i = 0; i < 3; i++) conv_B(g2W + i * DD, Bh, D_, D_, (size_t)i * 1024);
    mma_gemm<<<g3, 256, GEMM_SMEM>>>(Ah, Bh, yW, M_, 3072, D_, nullptr, 0);
    conv_A(src, Ah, (size_t)MD_);
    for (int i = 0; i < 3; i++) conv_B(g2U + i * DD, Bh, D_, D_, (size_t)i * 1024);
    mma_gemm<<<g3, 256, GEMM_SMEM>>>(Ah, Bh, xU, M_, 3072, D_, nullptr, 0);
    gru_kernel<<<MD_ / 256, 256>>>(src, yW, xU, g2bz, out);
}